// round 8
// baseline (speedup 1.0000x reference)
#include <cuda_runtime.h>
#include <math.h>

#define B_   8
#define T_   512
#define FIN_ 256
#define D_   128
#define C_   16          // chunks per batch
#define L_   32          // chunk length
#define KP_  132         // padded K pitch in k4 smem
#define AP_  33          // padded A pitch

typedef unsigned long long u64;

__device__ __forceinline__ void fma2(u64& acc, u64 a, u64 b) {
    asm("fma.rn.f32x2 %0, %1, %2, %3;" : "=l"(acc) : "l"(a), "l"(b), "l"(acc));
}
__device__ __forceinline__ u64 bc2(float a) {
    u64 r; asm("mov.b64 %0, {%1, %1};" : "=l"(r) : "f"(a)); return r;
}
__device__ __forceinline__ float2 unp2(u64 v) {
    float2 r; asm("mov.b64 {%0, %1}, %2;" : "=f"(r.x), "=f"(r.y) : "l"(v)); return r;
}

// ---------------- scratch ----------------
__device__ __align__(16) float g_XN[B_*T_*FIN_];
__device__ __align__(16) float g_K[B_*T_*D_];
__device__ __align__(16) float g_Q[B_*T_*D_];
__device__ __align__(16) float g_V[B_*T_*D_];
__device__ __align__(16) float g_R[B_*T_*D_];
__device__ __align__(16) float g_num[B_*T_*D_];
__device__ __align__(16) float g_den[B_*T_];
__device__ __align__(16) float g_Soff[B_*C_*D_*D_];
__device__ __align__(16) float g_Zsum[B_*C_*D_];

// ---------------- k0: LayerNorm ----------------
__global__ void k0_ln(const float* __restrict__ x, const float* __restrict__ gamma,
                      const float* __restrict__ beta) {
    const int tid  = threadIdx.x;         // 256
    const int w    = tid >> 5, lane = tid & 31;
    const int row0 = blockIdx.x * 32;

    float gv[8], bv[8];
#pragma unroll
    for (int k = 0; k < 8; k++) { gv[k] = gamma[lane + 32*k]; bv[k] = beta[lane + 32*k]; }

#pragma unroll
    for (int rr = 0; rr < 4; rr++) {
        const size_t r = (size_t)row0 + w*4 + rr;
        float s = 0.f, ss = 0.f, xv[8];
#pragma unroll
        for (int k = 0; k < 8; k++) {
            float v = x[r*FIN_ + lane + 32*k];
            xv[k] = v; s += v; ss += v*v;
        }
#pragma unroll
        for (int off = 16; off; off >>= 1) {
            s  += __shfl_xor_sync(0xffffffffu, s,  off);
            ss += __shfl_xor_sync(0xffffffffu, ss, off);
        }
        const float mu   = s * (1.0f/FIN_);
        const float rstd = rsqrtf(ss*(1.0f/FIN_) - mu*mu + 1e-5f);
#pragma unroll
        for (int k = 0; k < 8; k++)
            g_XN[r*FIN_ + lane + 32*k] = (xv[k]-mu)*rstd*gv[k] + bv[k];
    }
}

// ---------------- k1: 128x128 tile GEMM, 8x8 micro, f32x2 ----------------
#define XPITCH 36
__global__ void __launch_bounds__(256)
k1_proj(const float* __restrict__ Wk, const float* __restrict__ Wq,
        const float* __restrict__ Wv, const float* __restrict__ Ws,
        const float* __restrict__ bs) {
    __shared__ __align__(16) float xb[128*XPITCH];
    __shared__ __align__(16) float wb[32*D_];
    const int tid = threadIdx.x;
    const int tr  = tid >> 4;           // 0..15
    const int tc  = tid & 15;           // 0..15
    const int row0 = blockIdx.x * 128;
    const int m    = blockIdx.y;        // 0:K 1:Q 2:V 3:R

    const float* Wp = (m==0) ? Wk : (m==1) ? Wq : (m==2) ? Wv : Ws;
    float*       Op = (m==0) ? g_K : (m==1) ? g_Q : (m==2) ? g_V : g_R;

    u64 acc2[8][4];
#pragma unroll
    for (int u = 0; u < 8; u++)
#pragma unroll
        for (int p = 0; p < 4; p++) acc2[u][p] = 0ull;

    for (int kc = 0; kc < FIN_; kc += 32) {
        __syncthreads();
#pragma unroll
        for (int p = 0; p < 4; p++) {
            const int idx = p*256 + tid;
            const int r = idx >> 3, cc = idx & 7;
            const float4 v = *(const float4*)(g_XN + ((size_t)row0 + r)*FIN_ + kc + cc*4);
            *(float4*)&xb[r*XPITCH + cc*4] = v;
        }
#pragma unroll
        for (int p = 0; p < 4; p++) {
            const int idx = p*256 + tid;
            const int r = idx >> 5, cc = idx & 31;
            const float4 v = *(const float4*)(Wp + ((size_t)kc + r)*D_ + cc*4);
            *(float4*)&wb[r*D_ + cc*4] = v;
        }
        __syncthreads();

#pragma unroll
        for (int k = 0; k < 32; k += 2) {
            const ulonglong2 wa0 = *(const ulonglong2*)&wb[k*D_ + tc*8];
            const ulonglong2 wa1 = *(const ulonglong2*)&wb[k*D_ + tc*8 + 4];
            const ulonglong2 wb0 = *(const ulonglong2*)&wb[(k+1)*D_ + tc*8];
            const ulonglong2 wb1 = *(const ulonglong2*)&wb[(k+1)*D_ + tc*8 + 4];
#pragma unroll
            for (int u = 0; u < 8; u++) {
                const float2 xv = *(const float2*)&xb[(tr*8+u)*XPITCH + k];
                const u64 a0 = bc2(xv.x);
                const u64 a1 = bc2(xv.y);
                fma2(acc2[u][0], a0, wa0.x);
                fma2(acc2[u][1], a0, wa0.y);
                fma2(acc2[u][2], a0, wa1.x);
                fma2(acc2[u][3], a0, wa1.y);
                fma2(acc2[u][0], a1, wb0.x);
                fma2(acc2[u][1], a1, wb0.y);
                fma2(acc2[u][2], a1, wb1.x);
                fma2(acc2[u][3], a1, wb1.y);
            }
        }
    }

    float badd[8] = {0,0,0,0,0,0,0,0};
    if (m == 3) {
        float4 t0 = ((const float4*)bs)[tc*2];
        float4 t1 = ((const float4*)bs)[tc*2+1];
        badd[0]=t0.x; badd[1]=t0.y; badd[2]=t0.z; badd[3]=t0.w;
        badd[4]=t1.x; badd[5]=t1.y; badd[6]=t1.z; badd[7]=t1.w;
    }
#pragma unroll
    for (int u = 0; u < 8; u++) {
        float o[8];
#pragma unroll
        for (int p = 0; p < 4; p++) {
            const float2 t = unp2(acc2[u][p]);
            o[2*p] = t.x; o[2*p+1] = t.y;
        }
#pragma unroll
        for (int v = 0; v < 8; v++) {
            float val = o[v];
            if (m <= 1) val = (val > 0.f) ? (val + 1.f) : expf(val);   // elu + 1
            o[v] = val + badd[v];
        }
        float* dst = Op + ((size_t)(row0 + tr*8 + u))*D_ + tc*8;
        *(float4*)(dst)   = make_float4(o[0], o[1], o[2], o[3]);
        *(float4*)(dst+4) = make_float4(o[4], o[5], o[6], o[7]);
    }
}

// ---------------- k2_scan: fused chunk sums + exclusive scan (S and Z) ----------------
// grid (8 i-tiles, B) x 256. Block holds 16x128 running prefix in regs, walks c serially.
__global__ void __launch_bounds__(256)
k2_scan() {
    const int it = blockIdx.x, b = blockIdx.y;
    const int ib = it * 16;
    const int tid = threadIdx.x;
    const int ti = tid >> 4, tj = tid & 15;
    const int j0 = tj * 8;

    __shared__ __align__(16) float Kb[L_*16];
    __shared__ __align__(16) float Vb[L_*D_];

    float acc[8] = {0.f,0.f,0.f,0.f,0.f,0.f,0.f,0.f};
    float zacc = 0.f;

    for (int c = 0; c < C_; c++) {
        // exclusive prefix write (acc = sum of chunks < c)
        float* op = g_Soff + ((size_t)(b*C_ + c)*D_ + ib + ti)*D_ + j0;
        *(float4*)(op)     = make_float4(acc[0], acc[1], acc[2], acc[3]);
        *(float4*)(op + 4) = make_float4(acc[4], acc[5], acc[6], acc[7]);
        if (tid < 16)
            g_Zsum[(size_t)(b*C_ + c)*D_ + ib + tid] = zacc;
        __syncthreads();   // prev-iter smem reads done before overwrite

        // stage K slice [32 t][16 i] and V chunk [32 t][128 j]
        if (tid < 128) {
            const int t = tid >> 2, q = tid & 3;
            *(float4*)&Kb[t*16 + q*4] =
                *(const float4*)(g_K + ((size_t)b*T_ + c*L_ + t)*D_ + ib + q*4);
        }
#pragma unroll
        for (int p = 0; p < 4; p++) {
            const int idx = p*256 + tid;
            const int t = idx >> 5, q = idx & 31;
            *(float4*)&Vb[t*D_ + q*4] =
                *(const float4*)(g_V + ((size_t)b*T_ + c*L_ + t)*D_ + q*4);
        }
        __syncthreads();

#pragma unroll 8
        for (int t = 0; t < L_; t++) {
            const float kv = Kb[t*16 + ti];
            const float4 v0 = *(const float4*)&Vb[t*D_ + j0];
            const float4 v1 = *(const float4*)&Vb[t*D_ + j0 + 4];
            acc[0] += kv*v0.x; acc[1] += kv*v0.y; acc[2] += kv*v0.z; acc[3] += kv*v0.w;
            acc[4] += kv*v1.x; acc[5] += kv*v1.y; acc[6] += kv*v1.z; acc[7] += kv*v1.w;
        }
        if (tid < 16) {
#pragma unroll 8
            for (int t = 0; t < L_; t++) zacc += Kb[t*16 + tid];
        }
    }
}

// ---------------- k4: j-quarter streaming scan + num/den. grid (C_, B_, 4) x 256 ----------------
__global__ void __launch_bounds__(256, 4)
k4_scan(const float* __restrict__ S0, const float* __restrict__ Z0,
        float* __restrict__ outS, float* __restrict__ outZ) {
    const int c = blockIdx.x, b = blockIdx.y, jq = blockIdx.z;
    const int tid = threadIdx.x;         // 256
    const int ig = tid >> 3;             // 0..31
    const int jg = tid & 7;              // 0..7
    const int i0 = ig << 2;              // 0..124
    const int jb = jq * 32;              // quarter base
    const int jl = jg << 2;              // 0..28 local
    const int jglob = jb + jl;

    __shared__ __align__(16) float Ks[L_*KP_];   // padded pitch
    __shared__ __align__(16) float Qs[L_*D_];
    __shared__ __align__(16) float Vq[L_*32];
    __shared__ __align__(16) float A[L_*AP_];
    __shared__ float zv[D_];
    __shared__ float sden[L_];

    const size_t base = ((size_t)b*T_ + c*L_)*D_;

    // stage K (padded), Q, Vq
#pragma unroll
    for (int p = 0; p < 4; p++) {
        const int idx = p*256 + tid;
        const int t = idx >> 5, q = (idx & 31)*4;
        *(float4*)&Ks[t*KP_ + q] = *(const float4*)(g_K + base + (size_t)t*D_ + q);
        *(float4*)&Qs[t*D_  + q] = *(const float4*)(g_Q + base + (size_t)t*D_ + q);
    }
    {
        const int t = tid >> 3, q = (tid & 7)*4;
        *(float4*)&Vq[t*32 + q] = *(const float4*)(g_V + base + (size_t)t*D_ + jb + q);
    }

    // state init
    float s[4][4];
    {
        const float* soff = g_Soff + ((size_t)(b*C_ + c)*D_ + i0)*D_ + jglob;
        const float* s0g  = S0 + ((size_t)b*D_ + i0)*D_ + jglob;
#pragma unroll
        for (int u = 0; u < 4; u++) {
            const float4 a = *(const float4*)(soff + (size_t)u*D_);
            const float4 z = *(const float4*)(s0g  + (size_t)u*D_);
            s[u][0] = a.x + z.x; s[u][1] = a.y + z.y;
            s[u][2] = a.z + z.z; s[u][3] = a.w + z.w;
        }
    }
    float zrun = 0.f;
    if (jq == 0 && tid < D_) {
        zrun = Z0[b*D_ + tid] + g_Zsum[(size_t)(b*C_ + c)*D_ + tid];
        zv[tid] = zrun;
    }
    __syncthreads();

    // phase 1: streaming scan, no syncs
    {
        float* op = outS + ((size_t)(b*T_ + c*L_))*D_*D_ + (size_t)i0*D_ + jglob;
        float* zp = outZ + base;
        for (int tt = 0; tt < L_; tt++) {
            const float4 kv = *(const float4*)&Ks[tt*KP_ + i0];
            const float4 vv = *(const float4*)&Vq[tt*32 + jl];
            const float kk[4] = {kv.x, kv.y, kv.z, kv.w};
#pragma unroll
            for (int u = 0; u < 4; u++) {
                s[u][0] += kk[u]*vv.x;
                s[u][1] += kk[u]*vv.y;
                s[u][2] += kk[u]*vv.z;
                s[u][3] += kk[u]*vv.w;
                __stcs((float4*)(op + (size_t)u*D_),
                       make_float4(s[u][0], s[u][1], s[u][2], s[u][3]));
            }
            if (jq == 0 && tid < D_) { zrun += Ks[tt*KP_ + tid]; zp[tid] = zrun; }
            op += (size_t)D_*D_;
            zp += D_;
        }
    }

    // phase 2a: masked A = QK^T (all threads: ti=tid>>3, g=tid&7); den on jq==0
    {
        const int ti = tid >> 3;
        const int g  = tid & 7;
        float a4[4] = {0.f, 0.f, 0.f, 0.f};
        for (int k = 0; k < D_; k += 4) {
            const float4 qv = *(const float4*)&Qs[ti*D_ + k];
#pragma unroll
            for (int j = 0; j < 4; j++) {
                const float4 kv = *(const float4*)&Ks[(g*4+j)*KP_ + k];
                a4[j] += qv.x*kv.x + qv.y*kv.y + qv.z*kv.z + qv.w*kv.w;
            }
        }
        float rsum = 0.f;
#pragma unroll
        for (int j = 0; j < 4; j++) {
            const int tj = g*4 + j;
            const float mval = (tj <= ti) ? a4[j] : 0.f;
            A[ti*AP_ + tj] = mval;
            rsum += mval;
        }
        if (jq == 0) {
            float zp = 0.f;
#pragma unroll
            for (int k = 0; k < 16; k += 4) {
                const float4 qv = *(const float4*)&Qs[ti*D_ + g*16 + k];
                const float4 zz = *(const float4*)&zv[g*16 + k];
                zp += qv.x*zz.x + qv.y*zz.y + qv.z*zz.z + qv.w*zz.w;
            }
            float tot = rsum + zp;
#pragma unroll
            for (int off = 4; off; off >>= 1) tot += __shfl_down_sync(0xffffffffu, tot, off);
            if (g == 0) sden[ti] = tot;
        }
    }
    __syncthreads();

    if (jq == 0 && tid < L_)
        g_den[(size_t)b*T_ + c*L_ + tid] = sden[tid];

    // phase 2b: numerator quarter. row = tid>>3 (32), cg = (tid&7)*4 (32 local cols)
    const int row = tid >> 3;
    const int cg  = (tid & 7) * 4;
    float nacc[4] = {0.f, 0.f, 0.f, 0.f};
    // intra: masked A @ Vq (must finish before Vq is reused as staging)
    for (int tj = 0; tj <= row; tj++) {
        const float a = A[row*AP_ + tj];
        const float4 vv = *(const float4*)&Vq[tj*32 + cg];
        nacc[0] += a*vv.x; nacc[1] += a*vv.y;
        nacc[2] += a*vv.z; nacc[3] += a*vv.w;
    }
    // inter: Q @ (S0+Soff) quarter, staged 32 k-rows x 32 cols into Vq
    {
        const float* s0p = S0 + (size_t)b*D_*D_ + jb;
        const float* sop = g_Soff + (size_t)(b*C_ + c)*D_*D_ + jb;
        for (int kb = 0; kb < D_; kb += 32) {
            __syncthreads();
            {
                const int r = tid >> 3;
                const int q = (tid & 7)*4;
                const float4 x0 = __ldg((const float4*)(s0p + (size_t)(kb + r)*D_ + q));
                const float4 x1 = __ldg((const float4*)(sop + (size_t)(kb + r)*D_ + q));
                *(float4*)&Vq[r*32 + q] = make_float4(x0.x+x1.x, x0.y+x1.y, x0.z+x1.z, x0.w+x1.w);
            }
            __syncthreads();
#pragma unroll 8
            for (int k = 0; k < 32; k++) {
                const float qq = Qs[row*D_ + kb + k];
                const float4 sv = *(const float4*)&Vq[k*32 + cg];
                nacc[0] += qq*sv.x; nacc[1] += qq*sv.y;
                nacc[2] += qq*sv.z; nacc[3] += qq*sv.w;
            }
        }
    }
    *(float4*)(g_num + base + (size_t)row*D_ + jb + cg) =
        make_float4(nacc[0], nacc[1], nacc[2], nacc[3]);
}

// ---------------- k5: FFN + residual ----------------
__global__ void k5_ffn(const float* __restrict__ W1, const float* __restrict__ b1_,
                       const float* __restrict__ W2, const float* __restrict__ b2_,
                       float* __restrict__ outO) {
    __shared__ __align__(16) float aBuf[32*D_];
    __shared__ __align__(16) float wBuf[32*D_];
    const int tid  = threadIdx.x;  // 256
    const int w    = tid >> 5, lane = tid & 31;
    const int row0 = blockIdx.x * 32;

#pragma unroll
    for (int rr = 0; rr < 4; rr++) {
        const int r = w*4 + rr;
        const size_t row = (size_t)row0 + r;
        const float rden = 1.0f / (g_den[row] + 1e-5f);
#pragma unroll
        for (int k = 0; k < 4; k++) {
            const int f = lane + 32*k;
            aBuf[r*D_ + f] = g_num[row*D_ + f] * rden;
        }
    }
    const int rowg = w, colg = lane;
    float acc[4][4];

#pragma unroll
    for (int u = 0; u < 4; u++)
#pragma unroll
        for (int v = 0; v < 4; v++) acc[u][v] = 0.f;
    for (int kc = 0; kc < D_; kc += 32) {
        __syncthreads();
        for (int q = tid; q < 32*D_/4; q += 256)
            ((float4*)wBuf)[q] = ((const float4*)(W1 + (size_t)kc*D_))[q];
        __syncthreads();
#pragma unroll
        for (int k = 0; k < 32; k++) {
            const float4 wv = ((const float4*)(wBuf + k*D_))[colg];
#pragma unroll
            for (int u = 0; u < 4; u++) {
                const float a = aBuf[(rowg*4+u)*D_ + kc + k];
                acc[u][0] += a*wv.x; acc[u][1] += a*wv.y;
                acc[u][2] += a*wv.z; acc[u][3] += a*wv.w;
            }
        }
    }
    __syncthreads();
    {
        const float4 b1v = ((const float4*)b1_)[colg];
#pragma unroll
        for (int u = 0; u < 4; u++) {
            float4 h;
            h.x = fmaxf(acc[u][0] + b1v.x, 0.f);
            h.y = fmaxf(acc[u][1] + b1v.y, 0.f);
            h.z = fmaxf(acc[u][2] + b1v.z, 0.f);
            h.w = fmaxf(acc[u][3] + b1v.w, 0.f);
            *(float4*)&aBuf[(rowg*4+u)*D_ + colg*4] = h;
        }
    }
#pragma unroll
    for (int u = 0; u < 4; u++)
#pragma unroll
        for (int v = 0; v < 4; v++) acc[u][v] = 0.f;
    for (int kc = 0; kc < D_; kc += 32) {
        __syncthreads();
        for (int q = tid; q < 32*D_/4; q += 256)
            ((float4*)wBuf)[q] = ((const float4*)(W2 + (size_t)kc*D_))[q];
        __syncthreads();
#pragma unroll
        for (int k = 0; k < 32; k++) {
            const float4 wv = ((const float4*)(wBuf + k*D_))[colg];
#pragma unroll
            for (int u = 0; u < 4; u++) {
                const float a = aBuf[(rowg*4+u)*D_ + kc + k];
                acc[u][0] += a*wv.x; acc[u][1] += a*wv.y;
                acc[u][2] += a*wv.z; acc[u][3] += a*wv.w;
            }
        }
    }
    {
        const float4 b2v = ((const float4*)b2_)[colg];
#pragma unroll
        for (int u = 0; u < 4; u++) {
            const size_t row = (size_t)row0 + rowg*4 + u;
            const float4 rv = *(const float4*)(g_R + row*D_ + colg*4);
            float4 o;
            o.x = fmaxf(acc[u][0] + b2v.x, 0.f) + rv.x;
            o.y = fmaxf(acc[u][1] + b2v.y, 0.f) + rv.y;
            o.z = fmaxf(acc[u][2] + b2v.z, 0.f) + rv.z;
            o.w = fmaxf(acc[u][3] + b2v.w, 0.f) + rv.w;
            *(float4*)(outO + row*D_ + colg*4) = o;
        }
    }
}

// ---------------- launch ----------------
extern "C" void kernel_launch(void* const* d_in, const int* in_sizes, int n_in,
                              void* d_out, int out_size) {
    const float* x     = (const float*)d_in[0];
    const float* S0    = (const float*)d_in[1];
    const float* Z0    = (const float*)d_in[2];
    const float* gamma = (const float*)d_in[3];
    const float* beta  = (const float*)d_in[4];
    const float* Wk    = (const float*)d_in[5];
    const float* Wq    = (const float*)d_in[6];
    const float* Wv    = (const float*)d_in[7];
    const float* W1    = (const float*)d_in[8];
    const float* b1    = (const float*)d_in[9];
    const float* W2    = (const float*)d_in[10];
    const float* b2    = (const float*)d_in[11];
    const float* Ws    = (const float*)d_in[12];
    const float* bs    = (const float*)d_in[13];

    float* outO = (float*)d_out;
    float* outS = outO + (size_t)B_*T_*D_;
    float* outZ = outS + (size_t)B_*T_*D_*D_;

    k0_ln<<<(B_*T_)/32, 256>>>(x, gamma, beta);
    k1_proj<<<dim3((B_*T_)/128, 4), 256>>>(Wk, Wq, Wv, Ws, bs);
    k2_scan<<<dim3(8, B_), 256>>>();
    k4_scan<<<dim3(C_, B_, 4), 256>>>(S0, Z0, outS, outZ);
    k5_ffn<<<(B_*T_)/32, 256>>>(W1, b1, W2, b2, outO);
}

// round 9
// speedup vs baseline: 1.2772x; 1.2772x over previous
#include <cuda_runtime.h>
#include <math.h>

#define B_   8
#define T_   512
#define FIN_ 256
#define D_   128
#define C_   16
#define L_   32
#define JH_  64
#define XPITCH 36

typedef unsigned long long u64;

__device__ __forceinline__ void fma2(u64& acc, u64 a, u64 b) {
    asm("fma.rn.f32x2 %0, %1, %2, %3;" : "=l"(acc) : "l"(a), "l"(b), "l"(acc));
}
__device__ __forceinline__ u64 bc2(float a) {
    u64 r; asm("mov.b64 %0, {%1, %1};" : "=l"(r) : "f"(a)); return r;
}
__device__ __forceinline__ float2 unp2(u64 v) {
    float2 r; asm("mov.b64 {%0, %1}, %2;" : "=f"(r.x), "=f"(r.y) : "l"(v)); return r;
}

// ---------------- scratch ----------------
__device__ __align__(16) float g_XN[B_*T_*FIN_];
__device__ __align__(16) float g_K[B_*T_*D_];
__device__ __align__(16) float g_Q[B_*T_*D_];
__device__ __align__(16) float g_V[B_*T_*D_];
__device__ __align__(16) float g_R[B_*T_*D_];
__device__ __align__(16) float g_num[B_*T_*D_];
__device__ __align__(16) float g_den[B_*T_];
__device__ __align__(16) float g_Soff[B_*C_*D_*D_];
__device__ __align__(16) float g_Zsum[B_*C_*D_];

// ---------------- k0: LayerNorm ----------------
__global__ void k0_ln(const float* __restrict__ x, const float* __restrict__ gamma,
                      const float* __restrict__ beta) {
    const int tid  = threadIdx.x;         // 256
    const int w    = tid >> 5, lane = tid & 31;
    const int row0 = blockIdx.x * 32;

    float gv[8], bv[8];
#pragma unroll
    for (int k = 0; k < 8; k++) { gv[k] = gamma[lane + 32*k]; bv[k] = beta[lane + 32*k]; }

#pragma unroll
    for (int rr = 0; rr < 4; rr++) {
        const size_t r = (size_t)row0 + w*4 + rr;
        float s = 0.f, ss = 0.f, xv[8];
#pragma unroll
        for (int k = 0; k < 8; k++) {
            float v = x[r*FIN_ + lane + 32*k];
            xv[k] = v; s += v; ss += v*v;
        }
#pragma unroll
        for (int off = 16; off; off >>= 1) {
            s  += __shfl_xor_sync(0xffffffffu, s,  off);
            ss += __shfl_xor_sync(0xffffffffu, ss, off);
        }
        const float mu   = s * (1.0f/FIN_);
        const float rstd = rsqrtf(ss*(1.0f/FIN_) - mu*mu + 1e-5f);
#pragma unroll
        for (int k = 0; k < 8; k++)
            g_XN[r*FIN_ + lane + 32*k] = (xv[k]-mu)*rstd*gv[k] + bv[k];
    }
}

// ---------------- k1 v4: 128x128 tile, f32x2, conflict-aware col split ----------------
// 256 threads: tr=tid>>4 rows tr*8..+8, tc=tid&15 cols {tc*4, 64+tc*4}
__global__ void __launch_bounds__(256)
k1_proj(const float* __restrict__ Wk, const float* __restrict__ Wq,
        const float* __restrict__ Wv, const float* __restrict__ Ws,
        const float* __restrict__ bs) {
    __shared__ __align__(16) float xb[128*XPITCH];
    __shared__ __align__(16) float wb[32*D_];
    const int tid = threadIdx.x;
    const int tr  = tid >> 4;           // 0..15
    const int tc  = tid & 15;           // 0..15
    const int row0 = blockIdx.x * 128;
    const int m    = blockIdx.y;        // 0:K 1:Q 2:V 3:R

    const float* Wp = (m==0) ? Wk : (m==1) ? Wq : (m==2) ? Wv : Ws;
    float*       Op = (m==0) ? g_K : (m==1) ? g_Q : (m==2) ? g_V : g_R;

    u64 acc2[8][4];
#pragma unroll
    for (int u = 0; u < 8; u++)
#pragma unroll
        for (int p = 0; p < 4; p++) acc2[u][p] = 0ull;

    for (int kc = 0; kc < FIN_; kc += 32) {
        __syncthreads();
        // stage x: 128 rows x 32 k
#pragma unroll
        for (int p = 0; p < 4; p++) {
            const int idx = p*256 + tid;
            const int r = idx >> 3, cc = idx & 7;
            const float4 v = *(const float4*)(g_XN + ((size_t)row0 + r)*FIN_ + kc + cc*4);
            *(float4*)&xb[r*XPITCH + cc*4] = v;
        }
        // stage w: 32 k x 128 cols
#pragma unroll
        for (int p = 0; p < 4; p++) {
            const int idx = p*256 + tid;
            const int r = idx >> 5, cc = idx & 31;
            const float4 v = *(const float4*)(Wp + ((size_t)kc + r)*D_ + cc*4);
            *(float4*)&wb[r*D_ + cc*4] = v;
        }
        __syncthreads();

#pragma unroll
        for (int k = 0; k < 32; k++) {
            const ulonglong2 w0 = *(const ulonglong2*)&wb[k*D_ + tc*4];        // cols tc*4..+3
            const ulonglong2 w1 = *(const ulonglong2*)&wb[k*D_ + 64 + tc*4];   // cols 64+tc*4..+3
#pragma unroll
            for (int u = 0; u < 8; u++) {
                const u64 a = bc2(xb[(tr*8+u)*XPITCH + k]);
                fma2(acc2[u][0], a, w0.x);
                fma2(acc2[u][1], a, w0.y);
                fma2(acc2[u][2], a, w1.x);
                fma2(acc2[u][3], a, w1.y);
            }
        }
    }

    float badd[8] = {0,0,0,0,0,0,0,0};
    if (m == 3) {
        const float4 t0 = *(const float4*)(bs + tc*4);
        const float4 t1 = *(const float4*)(bs + 64 + tc*4);
        badd[0]=t0.x; badd[1]=t0.y; badd[2]=t0.z; badd[3]=t0.w;
        badd[4]=t1.x; badd[5]=t1.y; badd[6]=t1.z; badd[7]=t1.w;
    }
#pragma unroll
    for (int u = 0; u < 8; u++) {
        float o[8];
#pragma unroll
        for (int p = 0; p < 4; p++) {
            const float2 t = unp2(acc2[u][p]);
            o[2*p] = t.x; o[2*p+1] = t.y;
        }
#pragma unroll
        for (int v = 0; v < 8; v++) {
            float val = o[v];
            if (m <= 1) val = (val > 0.f) ? (val + 1.f) : expf(val);   // elu + 1
            o[v] = val + badd[v];
        }
        float* dst = Op + ((size_t)(row0 + tr*8 + u))*D_;
        *(float4*)(dst + tc*4)      = make_float4(o[0], o[1], o[2], o[3]);
        *(float4*)(dst + 64 + tc*4) = make_float4(o[4], o[5], o[6], o[7]);
    }
}

// ---------------- k2: per-chunk outer-product sums + K sums ----------------
__global__ void k2_chunksum() {
    const int c = blockIdx.x, b = blockIdx.y;
    const int tid = threadIdx.x;   // 256
    __shared__ __align__(16) float Ks[L_][D_];
    __shared__ __align__(16) float Vs[L_][D_];
    {
        const float4* kg = (const float4*)(g_K + ((size_t)b*T_ + c*L_)*D_);
        const float4* vg = (const float4*)(g_V + ((size_t)b*T_ + c*L_)*D_);
        for (int q = tid; q < L_*D_/4; q += 256) { ((float4*)Ks)[q] = kg[q]; ((float4*)Vs)[q] = vg[q]; }
    }
    __syncthreads();

    if (tid < D_) {
        float zs = 0.f;
#pragma unroll
        for (int t = 0; t < L_; t++) zs += Ks[t][tid];
        g_Zsum[((size_t)(b*C_ + c))*D_ + tid] = zs;
    }

    const int tr = tid >> 4, tc = tid & 15;
    const int i0 = tr*8, j0 = tc*8;
    float acc[8][8];
#pragma unroll
    for (int u = 0; u < 8; u++)
#pragma unroll
        for (int v = 0; v < 8; v++) acc[u][v] = 0.f;

    for (int t = 0; t < L_; t++) {
        float k8[8], v8[8];
        *(float4*)(k8)   = *(const float4*)&Ks[t][i0];
        *(float4*)(k8+4) = *(const float4*)&Ks[t][i0+4];
        *(float4*)(v8)   = *(const float4*)&Vs[t][j0];
        *(float4*)(v8+4) = *(const float4*)&Vs[t][j0+4];
#pragma unroll
        for (int u = 0; u < 8; u++)
#pragma unroll
            for (int v = 0; v < 8; v++) acc[u][v] += k8[u]*v8[v];
    }
    float* op = g_Soff + (((size_t)(b*C_ + c))*D_ + i0)*D_ + j0;
#pragma unroll
    for (int u = 0; u < 8; u++) {
        *(float4*)(op + (size_t)u*D_)     = make_float4(acc[u][0],acc[u][1],acc[u][2],acc[u][3]);
        *(float4*)(op + (size_t)u*D_ + 4) = make_float4(acc[u][4],acc[u][5],acc[u][6],acc[u][7]);
    }
}

// ---------------- k3: exclusive scan over c, float4-wide ----------------
__global__ void k3_scan() {
    const int gid = blockIdx.x * blockDim.x + threadIdx.x;
    if (gid < B_*D_*D_/4) {
        const int b = gid >> 12;
        const int q = gid & 4095;
        float4* p = ((float4*)g_Soff) + (size_t)b*C_*4096 + q;
        float4 v[C_];
#pragma unroll
        for (int c = 0; c < C_; c++) v[c] = p[(size_t)c*4096];
        float rx=0.f, ry=0.f, rz=0.f, rw=0.f;
#pragma unroll
        for (int c = 0; c < C_; c++) {
            const float4 t = v[c];
            v[c] = make_float4(rx, ry, rz, rw);
            rx += t.x; ry += t.y; rz += t.z; rw += t.w;
        }
#pragma unroll
        for (int c = 0; c < C_; c++) p[(size_t)c*4096] = v[c];
    } else if (gid < B_*D_*D_/4 + B_*D_/4) {
        const int zid = gid - B_*D_*D_/4;
        const int b = zid >> 5, q = zid & 31;
        float4* p = ((float4*)g_Zsum) + (size_t)b*C_*32 + q;
        float4 v[C_];
#pragma unroll
        for (int c = 0; c < C_; c++) v[c] = p[(size_t)c*32];
        float rx=0.f, ry=0.f, rz=0.f, rw=0.f;
#pragma unroll
        for (int c = 0; c < C_; c++) {
            const float4 t = v[c];
            v[c] = make_float4(rx, ry, rz, rw);
            rx += t.x; ry += t.y; rz += t.z; rw += t.w;
        }
#pragma unroll
        for (int c = 0; c < C_; c++) p[(size_t)c*32] = v[c];
    }
}

// ---------------- k4: j-split streaming scan + num/den. grid (C_, B_, 2) x 512 ----------------
__global__ void __launch_bounds__(512, 2)
k4_scan(const float* __restrict__ S0, const float* __restrict__ Z0,
        float* __restrict__ outS, float* __restrict__ outZ) {
    const int c = blockIdx.x, b = blockIdx.y, jh = blockIdx.z;
    const int tid = threadIdx.x;         // 512
    const int ig = tid >> 4;             // 0..31
    const int jg = tid & 15;             // 0..15
    const int i0 = ig << 2;
    const int j0 = jg << 2;
    const int jbase = jh * JH_;

    __shared__ __align__(16) float Ks[L_*D_];
    __shared__ __align__(16) float Qs[L_*D_];
    __shared__ __align__(16) float Vh[L_*JH_];
    __shared__ __align__(16) float A[L_*L_];
    __shared__ float zv[D_];
    __shared__ float sden[L_];

    const size_t base = ((size_t)b*T_ + c*L_)*D_;

    {
        ((float4*)Ks)[tid]       = ((const float4*)(g_K + base))[tid];
        ((float4*)Ks)[tid + 512] = ((const float4*)(g_K + base))[tid + 512];
        ((float4*)Qs)[tid]       = ((const float4*)(g_Q + base))[tid];
        ((float4*)Qs)[tid + 512] = ((const float4*)(g_Q + base))[tid + 512];
        const int t = tid >> 4;
        const int q = tid & 15;
        ((float4*)Vh)[tid] = *(const float4*)(g_V + base + (size_t)t*D_ + jbase + q*4);
    }

    float s[4][4];
    {
        const float* soff = g_Soff + ((size_t)(b*C_ + c)*D_ + i0)*D_ + jbase + j0;
        const float* s0g  = S0 + ((size_t)b*D_ + i0)*D_ + jbase + j0;
#pragma unroll
        for (int u = 0; u < 4; u++) {
            const float4 a = *(const float4*)(soff + (size_t)u*D_);
            const float4 z = *(const float4*)(s0g  + (size_t)u*D_);
            s[u][0] = a.x + z.x; s[u][1] = a.y + z.y;
            s[u][2] = a.z + z.z; s[u][3] = a.w + z.w;
        }
    }
    float zrun = 0.f;
    if (tid < D_) {
        zrun = Z0[b*D_ + tid] + g_Zsum[(size_t)(b*C_ + c)*D_ + tid];
        if (jh == 0) zv[tid] = zrun;
    }
    __syncthreads();

    // phase 1: streaming scan
    {
        float* op = outS + ((size_t)(b*T_ + c*L_))*D_*D_ + (size_t)i0*D_ + jbase + j0;
        float* zp = outZ + base;
        for (int tt = 0; tt < L_; tt++) {
            const float4 kv = *(const float4*)&Ks[tt*D_ + i0];
            const float4 vv = *(const float4*)&Vh[tt*JH_ + j0];
            const float kk[4] = {kv.x, kv.y, kv.z, kv.w};
#pragma unroll
            for (int u = 0; u < 4; u++) {
                s[u][0] += kk[u]*vv.x;
                s[u][1] += kk[u]*vv.y;
                s[u][2] += kk[u]*vv.z;
                s[u][3] += kk[u]*vv.w;
                __stcs((float4*)(op + (size_t)u*D_),
                       make_float4(s[u][0], s[u][1], s[u][2], s[u][3]));
            }
            if (jh == 0 && tid < D_) { zrun += Ks[tt*D_ + tid]; zp[tid] = zrun; }
            op += (size_t)D_*D_;
            zp += D_;
        }
    }

    // phase 2a: masked A = QK^T; den on jh==0
    if (tid < 256) {
        const int ti = tid >> 3;
        const int g  = tid & 7;
        float a4[4] = {0.f, 0.f, 0.f, 0.f};
        for (int k = 0; k < D_; k += 4) {
            const float4 qv = *(const float4*)&Qs[ti*D_ + k];
#pragma unroll
            for (int j = 0; j < 4; j++) {
                const float4 kv = *(const float4*)&Ks[(g*4+j)*D_ + k];
                a4[j] += qv.x*kv.x + qv.y*kv.y + qv.z*kv.z + qv.w*kv.w;
            }
        }
        float rsum = 0.f;
#pragma unroll
        for (int j = 0; j < 4; j++) {
            const int tj = g*4 + j;
            const float mval = (tj <= ti) ? a4[j] : 0.f;
            A[ti*L_ + tj] = mval;
            rsum += mval;
        }
        if (jh == 0) {
            float zp = 0.f;
#pragma unroll
            for (int k = 0; k < 16; k += 4) {
                const float4 qv = *(const float4*)&Qs[ti*D_ + g*16 + k];
                const float4 zz = *(const float4*)&zv[g*16 + k];
                zp += qv.x*zz.x + qv.y*zz.y + qv.z*zz.z + qv.w*zz.w;
            }
            float tot = rsum + zp;
#pragma unroll
            for (int off = 4; off; off >>= 1) tot += __shfl_down_sync(0xffffffffu, tot, off);
            if (g == 0) sden[ti] = tot;
        }
    }
    __syncthreads();

    // phase 2b: numerator half
    const int row = tid >> 4;
    const int cg  = (tid & 15) * 4;
    float nacc[4] = {0.f, 0.f, 0.f, 0.f};
    for (int tj = 0; tj <= row; tj++) {
        const float a = A[row*L_ + tj];
        const float4 vv = *(const float4*)&Vh[tj*JH_ + cg];
        nacc[0] += a*vv.x; nacc[1] += a*vv.y;
        nacc[2] += a*vv.z; nacc[3] += a*vv.w;
    }
    {
        const float* s0p = S0 + (size_t)b*D_*D_ + jbase;
        const float* sop = g_Soff + (size_t)(b*C_ + c)*D_*D_ + jbase;
        for (int kb = 0; kb < D_; kb += 32) {
            __syncthreads();
            {
                const int r = tid >> 4;
                const int q = tid & 15;
                const float4 x0 = __ldg((const float4*)(s0p + (size_t)(kb + r)*D_) + q);
                const float4 x1 = __ldg((const float4*)(sop + (size_t)(kb + r)*D_) + q);
                ((float4*)Vh)[tid] = make_float4(x0.x+x1.x, x0.y+x1.y, x0.z+x1.z, x0.w+x1.w);
            }
            __syncthreads();
#pragma unroll 8
            for (int k = 0; k < 32; k++) {
                const float qq = Qs[row*D_ + kb + k];
                const float4 sv = *(const float4*)&Vh[k*JH_ + cg];
                nacc[0] += qq*sv.x; nacc[1] += qq*sv.y;
                nacc[2] += qq*sv.z; nacc[3] += qq*sv.w;
            }
        }
    }
    *(float4*)(g_num + base + (size_t)row*D_ + jbase + cg) =
        make_float4(nacc[0], nacc[1], nacc[2], nacc[3]);
    if (jh == 0 && tid < L_)
        g_den[(size_t)b*T_ + c*L_ + tid] = sden[tid];
}

// ---------------- k5: FFN + residual ----------------
__global__ void k5_ffn(const float* __restrict__ W1, const float* __restrict__ b1_,
                       const float* __restrict__ W2, const float* __restrict__ b2_,
                       float* __restrict__ outO) {
    __shared__ __align__(16) float aBuf[32*D_];
    __shared__ __align__(16) float wBuf[32*D_];
    const int tid  = threadIdx.x;  // 256
    const int w    = tid >> 5, lane = tid & 31;
    const int row0 = blockIdx.x * 32;

#pragma unroll
    for (int rr = 0; rr < 4; rr++) {
        const int r = w*4 + rr;
        const size_t row = (size_t)row0 + r;
        const float rden = 1.0f / (g_den[row] + 1e-5f);
#pragma unroll
        for (int k = 0; k < 4; k++) {
            const int f = lane + 32*k;
            aBuf[r*D_ + f] = g_num[row*D_ + f] * rden;
        }
    }
    const int rowg = w, colg = lane;
    float acc[4][4];

#pragma unroll
    for (int u = 0; u < 4; u++)
#pragma unroll
        for (int v = 0; v < 4; v++) acc[u][v] = 0.f;
    for (int kc = 0; kc < D_; kc += 32) {
        __syncthreads();
        for (int q = tid; q < 32*D_/4; q += 256)
            ((float4*)wBuf)[q] = ((const float4*)(W1 + (size_t)kc*D_))[q];
        __syncthreads();
#pragma unroll
        for (int k = 0; k < 32; k++) {
            const float4 wv = ((const float4*)(wBuf + k*D_))[colg];
#pragma unroll
            for (int u = 0; u < 4; u++) {
                const float a = aBuf[(rowg*4+u)*D_ + kc + k];
                acc[u][0] += a*wv.x; acc[u][1] += a*wv.y;
                acc[u][2] += a*wv.z; acc[u][3] += a*wv.w;
            }
        }
    }
    __syncthreads();
    {
        const float4 b1v = ((const float4*)b1_)[colg];
#pragma unroll
        for (int u = 0; u < 4; u++) {
            float4 h;
            h.x = fmaxf(acc[u][0] + b1v.x, 0.f);
            h.y = fmaxf(acc[u][1] + b1v.y, 0.f);
            h.z = fmaxf(acc[u][2] + b1v.z, 0.f);
            h.w = fmaxf(acc[u][3] + b1v.w, 0.f);
            *(float4*)&aBuf[(rowg*4+u)*D_ + colg*4] = h;
        }
    }
#pragma unroll
    for (int u = 0; u < 4; u++)
#pragma unroll
        for (int v = 0; v < 4; v++) acc[u][v] = 0.f;
    for (int kc = 0; kc < D_; kc += 32) {
        __syncthreads();
        for (int q = tid; q < 32*D_/4; q += 256)
            ((float4*)wBuf)[q] = ((const float4*)(W2 + (size_t)kc*D_))[q];
        __syncthreads();
#pragma unroll
        for (int k = 0; k < 32; k++) {
            const float4 wv = ((const float4*)(wBuf + k*D_))[colg];
#pragma unroll
            for (int u = 0; u < 4; u++) {
                const float a = aBuf[(rowg*4+u)*D_ + kc + k];
                acc[u][0] += a*wv.x; acc[u][1] += a*wv.y;
                acc[u][2] += a*wv.z; acc[u][3] += a*wv.w;
            }
        }
    }
    {
        const float4 b2v = ((const float4*)b2_)[colg];
#pragma unroll
        for (int u = 0; u < 4; u++) {
            const size_t row = (size_t)row0 + rowg*4 + u;
            const float4 rv = *(const float4*)(g_R + row*D_ + colg*4);
            float4 o;
            o.x = fmaxf(acc[u][0] + b2v.x, 0.f) + rv.x;
            o.y = fmaxf(acc[u][1] + b2v.y, 0.f) + rv.y;
            o.z = fmaxf(acc[u][2] + b2v.z, 0.f) + rv.z;
            o.w = fmaxf(acc[u][3] + b2v.w, 0.f) + rv.w;
            *(float4*)(outO + row*D_ + colg*4) = o;
        }
    }
}

// ---------------- launch ----------------
extern "C" void kernel_launch(void* const* d_in, const int* in_sizes, int n_in,
                              void* d_out, int out_size) {
    const float* x     = (const float*)d_in[0];
    const float* S0    = (const float*)d_in[1];
    const float* Z0    = (const float*)d_in[2];
    const float* gamma = (const float*)d_in[3];
    const float* beta  = (const float*)d_in[4];
    const float* Wk    = (const float*)d_in[5];
    const float* Wq    = (const float*)d_in[6];
    const float* Wv    = (const float*)d_in[7];
    const float* W1    = (const float*)d_in[8];
    const float* b1    = (const float*)d_in[9];
    const float* W2    = (const float*)d_in[10];
    const float* b2    = (const float*)d_in[11];
    const float* Ws    = (const float*)d_in[12];
    const float* bs    = (const float*)d_in[13];

    float* outO = (float*)d_out;
    float* outS = outO + (size_t)B_*T_*D_;
    float* outZ = outS + (size_t)B_*T_*D_*D_;

    k0_ln<<<(B_*T_)/32, 256>>>(x, gamma, beta);
    k1_proj<<<dim3((B_*T_)/128, 4), 256>>>(Wk, Wq, Wv, Ws, bs);
    k2_chunksum<<<dim3(C_, B_), 256>>>();
    k3_scan<<<(B_*D_*D_/4 + B_*D_/4 + 255)/256, 256>>>();
    k4_scan<<<dim3(C_, B_, 2), 512>>>(S0, Z0, outS, outZ);
    k5_ffn<<<(B_*T_)/32, 256>>>(W1, b1, W2, b2, outO);
}

// round 10
// speedup vs baseline: 1.5187x; 1.1891x over previous
#include <cuda_runtime.h>
#include <math.h>

#define B_   8
#define T_   512
#define FIN_ 256
#define D_   128
#define C_   16          // chunks per batch
#define L_   32          // chunk length (T_/C_)
#define SUB_ 16          // sub-tile of timesteps kept in smem

// ---------------- scratch (device globals; no runtime allocation) ----------------
__device__ __align__(16) float g_XN[B_*T_*FIN_];   // normalized x
__device__ __align__(16) float g_K[B_*T_*D_];
__device__ __align__(16) float g_Q[B_*T_*D_];
__device__ __align__(16) float g_V[B_*T_*D_];
__device__ __align__(16) float g_R[B_*T_*D_];      // xn @ Ws + bs
__device__ __align__(16) float g_num[B_*T_*D_];    // numerator
__device__ __align__(16) float g_Ssum[B_*C_*D_*D_];// RAW per-chunk outer-product sums
__device__ __align__(16) float g_Zsum[B_*C_*D_];   // RAW per-chunk K sums

// ---------------- k0: LayerNorm -> g_XN ----------------
__global__ void k0_ln(const float* __restrict__ x,
                      const float* __restrict__ gamma, const float* __restrict__ beta) {
    const int tid  = threadIdx.x;
    const int w    = tid >> 5, lane = tid & 31;
    const int row0 = blockIdx.x * 32;

    float gv[8], bv[8];
#pragma unroll
    for (int k = 0; k < 8; k++) { gv[k] = gamma[lane + 32*k]; bv[k] = beta[lane + 32*k]; }

#pragma unroll
    for (int rr = 0; rr < 4; rr++) {
        const size_t r = (size_t)row0 + w*4 + rr;
        float s = 0.f, ss = 0.f, xv[8];
#pragma unroll
        for (int k = 0; k < 8; k++) {
            float v = x[r*FIN_ + lane + 32*k];
            xv[k] = v; s += v; ss += v*v;
        }
#pragma unroll
        for (int off = 16; off; off >>= 1) {
            s  += __shfl_xor_sync(0xffffffffu, s,  off);
            ss += __shfl_xor_sync(0xffffffffu, ss, off);
        }
        const float mu   = s * (1.0f/FIN_);
        const float rstd = rsqrtf(ss*(1.0f/FIN_) - mu*mu + 1e-5f);
#pragma unroll
        for (int k = 0; k < 8; k++)
            g_XN[r*FIN_ + lane + 32*k] = (xv[k]-mu)*rstd*gv[k] + bv[k];
    }
}

// ---------------- k1: projections (one matrix per blockIdx.y) — R2 version, plain fp32 ----------------
// grid (128, 4) x 128 threads, 32 rows/block, micro-tile 4x8
__global__ void k1_proj(const float* __restrict__ Wk, const float* __restrict__ Wq,
                        const float* __restrict__ Wv, const float* __restrict__ Ws,
                        const float* __restrict__ bs) {
    extern __shared__ float sm[];
    float* xb = sm;               // 32*256
    float* wb = sm + 32*FIN_;     // 32*128
    const int tid = threadIdx.x;       // 128
    const int tr  = tid >> 4;          // 0..7
    const int tc  = tid & 15;          // 0..15
    const int row0 = blockIdx.x * 32;
    const int m    = blockIdx.y;       // 0:K 1:Q 2:V 3:R

    const float* Wp = (m==0) ? Wk : (m==1) ? Wq : (m==2) ? Wv : Ws;
    float*       Op = (m==0) ? g_K : (m==1) ? g_Q : (m==2) ? g_V : g_R;

    // load xn tile
    {
        const float4* xg = (const float4*)(g_XN + (size_t)row0 * FIN_);
        for (int q = tid; q < 32*FIN_/4; q += 128) ((float4*)xb)[q] = xg[q];
    }

    float acc[4][8];
#pragma unroll
    for (int u = 0; u < 4; u++)
#pragma unroll
        for (int v = 0; v < 8; v++) acc[u][v] = 0.f;

    for (int kc = 0; kc < FIN_; kc += 32) {
        __syncthreads();
        for (int q = tid; q < 32*D_/4; q += 128)
            ((float4*)wb)[q] = ((const float4*)(Wp + (size_t)kc*D_))[q];
        __syncthreads();
#pragma unroll
        for (int k = 0; k < 32; k++) {
            const float4 wA = ((const float4*)(wb + k*D_))[tc*2];
            const float4 wB = ((const float4*)(wb + k*D_))[tc*2+1];
#pragma unroll
            for (int u = 0; u < 4; u++) {
                const float a = xb[(tr*4+u)*FIN_ + kc + k];
                acc[u][0] += a*wA.x; acc[u][1] += a*wA.y;
                acc[u][2] += a*wA.z; acc[u][3] += a*wA.w;
                acc[u][4] += a*wB.x; acc[u][5] += a*wB.y;
                acc[u][6] += a*wB.z; acc[u][7] += a*wB.w;
            }
        }
    }

    float badd[8] = {0,0,0,0,0,0,0,0};
    if (m == 3) {
        float4 t0 = ((const float4*)bs)[tc*2];
        float4 t1 = ((const float4*)bs)[tc*2+1];
        badd[0]=t0.x; badd[1]=t0.y; badd[2]=t0.z; badd[3]=t0.w;
        badd[4]=t1.x; badd[5]=t1.y; badd[6]=t1.z; badd[7]=t1.w;
    }
#pragma unroll
    for (int u = 0; u < 4; u++) {
        float o[8];
#pragma unroll
        for (int v = 0; v < 8; v++) {
            float val = acc[u][v];
            if (m <= 1) val = (val > 0.f) ? (val + 1.f) : expf(val);   // elu + 1
            o[v] = val + badd[v];
        }
        float* dst = Op + ((size_t)(row0 + tr*4 + u))*D_ + tc*8;
        *(float4*)(dst)   = make_float4(o[0], o[1], o[2], o[3]);
        *(float4*)(dst+4) = make_float4(o[4], o[5], o[6], o[7]);
    }
}

// ---------------- k2: per-chunk outer-product sums + per-chunk K sums (RAW, no scan) ----------------
__global__ void k2_chunksum() {
    const int c = blockIdx.x, b = blockIdx.y;
    const int tid = threadIdx.x;   // 256
    __shared__ __align__(16) float Ks[L_][D_];
    __shared__ __align__(16) float Vs[L_][D_];
    {
        const float4* kg = (const float4*)(g_K + ((size_t)b*T_ + c*L_)*D_);
        const float4* vg = (const float4*)(g_V + ((size_t)b*T_ + c*L_)*D_);
        for (int q = tid; q < L_*D_/4; q += 256) { ((float4*)Ks)[q] = kg[q]; ((float4*)Vs)[q] = vg[q]; }
    }
    __syncthreads();

    if (tid < D_) {
        float zs = 0.f;
#pragma unroll
        for (int t = 0; t < L_; t++) zs += Ks[t][tid];
        g_Zsum[((size_t)(b*C_ + c))*D_ + tid] = zs;
    }

    const int tr = tid >> 4, tc = tid & 15;  // 16x16, micro 8x8
    const int i0 = tr*8, j0 = tc*8;
    float acc[8][8];
#pragma unroll
    for (int u = 0; u < 8; u++)
#pragma unroll
        for (int v = 0; v < 8; v++) acc[u][v] = 0.f;

    for (int t = 0; t < L_; t++) {
        float k8[8], v8[8];
        *(float4*)(k8)   = *(const float4*)&Ks[t][i0];
        *(float4*)(k8+4) = *(const float4*)&Ks[t][i0+4];
        *(float4*)(v8)   = *(const float4*)&Vs[t][j0];
        *(float4*)(v8+4) = *(const float4*)&Vs[t][j0+4];
#pragma unroll
        for (int u = 0; u < 8; u++)
#pragma unroll
            for (int v = 0; v < 8; v++) acc[u][v] += k8[u]*v8[v];
    }
    float* op = g_Ssum + (((size_t)(b*C_ + c))*D_ + i0)*D_ + j0;
#pragma unroll
    for (int u = 0; u < 8; u++) {
        *(float4*)(op + (size_t)u*D_)     = make_float4(acc[u][0],acc[u][1],acc[u][2],acc[u][3]);
        *(float4*)(op + (size_t)u*D_ + 4) = make_float4(acc[u][4],acc[u][5],acc[u][6],acc[u][7]);
    }
}

// ---------------- k4: R2's fused scan — S state in regs, write S + Z, num inline ----------------
// init sums raw chunk sums (k3 eliminated)
__global__ void __launch_bounds__(1024, 1)
k4_main(const float* __restrict__ S0, const float* __restrict__ Z0,
        float* __restrict__ outS, float* __restrict__ outZ) {
    const int c = blockIdx.x, b = blockIdx.y;
    const int tid = threadIdx.x;         // 1024
    const int ri = tid >> 5;             // 0..31
    const int jg = tid & 31;             // 0..31
    const int i0 = ri << 2, j0 = jg << 2;

    extern __shared__ float dsm[];
    float* Ks   = dsm;                         // [SUB_][D_]
    float* Vs   = Ks + SUB_*D_;                // [SUB_][D_]
    float* Qs   = Vs + SUB_*D_;                // [SUB_][D_]
    float* part = Qs + SUB_*D_;                // [2][32][D_]

    // ---- init: S0 + sum of raw chunk sums c' < c (replaces k3's exclusive scan) ----
    float s[4][4];
    {
        const float* s0g = S0 + ((size_t)b*D_ + i0)*D_ + j0;
#pragma unroll
        for (int u = 0; u < 4; u++) {
            const float4 z = *(const float4*)(s0g + (size_t)u*D_);
            s[u][0] = z.x; s[u][1] = z.y; s[u][2] = z.z; s[u][3] = z.w;
        }
        for (int c2 = 0; c2 < c; c2++) {
            const float* sp = g_Ssum + ((size_t)(b*C_ + c2)*D_ + i0)*D_ + j0;
#pragma unroll
            for (int u = 0; u < 4; u++) {
                const float4 a = __ldg((const float4*)(sp + (size_t)u*D_));
                s[u][0] += a.x; s[u][1] += a.y; s[u][2] += a.z; s[u][3] += a.w;
            }
        }
    }

    float zrun = 0.f;
    if (tid < D_) {
        zrun = Z0[b*D_ + tid];
        for (int c2 = 0; c2 < c; c2++)
            zrun += g_Zsum[(size_t)(b*C_ + c2)*D_ + tid];
    }

    const int t0 = c * L_;
    for (int sub = 0; sub < L_/SUB_; sub++) {
        const int tg = t0 + sub*SUB_;
        {
            const float4* kg = (const float4*)(g_K + ((size_t)b*T_ + tg)*D_);
            const float4* vg = (const float4*)(g_V + ((size_t)b*T_ + tg)*D_);
            const float4* qg = (const float4*)(g_Q + ((size_t)b*T_ + tg)*D_);
            const int h = tid & 511;     // SUB_*D_/4 = 512
            if (tid < 512) { ((float4*)Ks)[h] = kg[h]; ((float4*)Vs)[h] = vg[h]; }
            else           { ((float4*)Qs)[h] = qg[h]; }
        }
        __syncthreads();

        for (int tt = 0; tt < SUB_; tt++) {
            const int t = tg + tt;
            const float4 kv = *(const float4*)&Ks[tt*D_ + i0];
            const float4 vv = *(const float4*)&Vs[tt*D_ + j0];
            const float4 qv = *(const float4*)&Qs[tt*D_ + i0];
            const float kk[4] = {kv.x, kv.y, kv.z, kv.w};
            const float vb[4] = {vv.x, vv.y, vv.z, vv.w};
            const float qq[4] = {qv.x, qv.y, qv.z, qv.w};
            float p0 = 0.f, p1 = 0.f, p2 = 0.f, p3 = 0.f;
            float* orow = outS + (((size_t)b*T_ + t)*D_ + i0)*D_ + j0;
#pragma unroll
            for (int u = 0; u < 4; u++) {
                s[u][0] += kk[u]*vb[0];
                s[u][1] += kk[u]*vb[1];
                s[u][2] += kk[u]*vb[2];
                s[u][3] += kk[u]*vb[3];
                __stcs((float4*)(orow + (size_t)u*D_),
                       make_float4(s[u][0], s[u][1], s[u][2], s[u][3]));
                p0 += qq[u]*s[u][0];
                p1 += qq[u]*s[u][1];
                p2 += qq[u]*s[u][2];
                p3 += qq[u]*s[u][3];
            }
            float* pb = part + (tt & 1)*32*D_;
            *(float4*)&pb[ri*D_ + j0] = make_float4(p0, p1, p2, p3);
            if (tid < D_) {
                zrun += Ks[tt*D_ + tid];
                outZ[((size_t)b*T_ + t)*D_ + tid] = zrun;
            }
            __syncthreads();
            if (tid < D_) {
                float sum = 0.f;
#pragma unroll
                for (int rr = 0; rr < 32; rr++) sum += pb[rr*D_ + tid];
                g_num[((size_t)b*T_ + t)*D_ + tid] = sum;
            }
        }
        __syncthreads();   // protect smem tiles before next sub reload
    }
}

// ---------------- k5: out = relu(relu((num/den)@W1+b1)@W2+b2) + R ----------------
__global__ void k5_ffn(const float* __restrict__ W1, const float* __restrict__ b1_,
                       const float* __restrict__ W2, const float* __restrict__ b2_,
                       const float* __restrict__ Zout, float* __restrict__ outO) {
    __shared__ __align__(16) float aBuf[32*D_];
    __shared__ __align__(16) float wBuf[32*D_];
    const int tid  = threadIdx.x;  // 256
    const int w    = tid >> 5, lane = tid & 31;
    const int row0 = blockIdx.x * 32;

    // denominator + a = num/den
#pragma unroll
    for (int rr = 0; rr < 4; rr++) {
        const int r = w*4 + rr;
        const size_t row = (size_t)row0 + r;
        float d = 0.f;
#pragma unroll
        for (int k = 0; k < 4; k++) {
            const int f = lane + 32*k;
            d += g_Q[row*D_ + f] * Zout[row*D_ + f];
        }
#pragma unroll
        for (int off = 16; off; off >>= 1) d += __shfl_xor_sync(0xffffffffu, d, off);
        const float rden = 1.0f / (d + 1e-5f);
#pragma unroll
        for (int k = 0; k < 4; k++) {
            const int f = lane + 32*k;
            aBuf[r*D_ + f] = g_num[row*D_ + f] * rden;
        }
    }
    const int rowg = w, colg = lane;
    float acc[4][4];

    // GEMM1: h = relu(a @ W1 + b1)
#pragma unroll
    for (int u = 0; u < 4; u++)
#pragma unroll
        for (int v = 0; v < 4; v++) acc[u][v] = 0.f;
    for (int kc = 0; kc < D_; kc += 32) {
        __syncthreads();
        for (int q = tid; q < 32*D_/4; q += 256)
            ((float4*)wBuf)[q] = ((const float4*)(W1 + (size_t)kc*D_))[q];
        __syncthreads();
#pragma unroll
        for (int k = 0; k < 32; k++) {
            const float4 wv = ((const float4*)(wBuf + k*D_))[colg];
#pragma unroll
            for (int u = 0; u < 4; u++) {
                const float a = aBuf[(rowg*4+u)*D_ + kc + k];
                acc[u][0] += a*wv.x; acc[u][1] += a*wv.y;
                acc[u][2] += a*wv.z; acc[u][3] += a*wv.w;
            }
        }
    }
    __syncthreads();
    {
        const float4 b1v = ((const float4*)b1_)[colg];
#pragma unroll
        for (int u = 0; u < 4; u++) {
            float4 h;
            h.x = fmaxf(acc[u][0] + b1v.x, 0.f);
            h.y = fmaxf(acc[u][1] + b1v.y, 0.f);
            h.z = fmaxf(acc[u][2] + b1v.z, 0.f);
            h.w = fmaxf(acc[u][3] + b1v.w, 0.f);
            *(float4*)&aBuf[(rowg*4+u)*D_ + colg*4] = h;
        }
    }
    // GEMM2: o = relu(h @ W2 + b2) + R
#pragma unroll
    for (int u = 0; u < 4; u++)
#pragma unroll
        for (int v = 0; v < 4; v++) acc[u][v] = 0.f;
    for (int kc = 0; kc < D_; kc += 32) {
        __syncthreads();
        for (int q = tid; q < 32*D_/4; q += 256)
            ((float4*)wBuf)[q] = ((const float4*)(W2 + (size_t)kc*D_))[q];
        __syncthreads();
#pragma unroll
        for (int k = 0; k < 32; k++) {
            const float4 wv = ((const float4*)(wBuf + k*D_))[colg];
#pragma unroll
            for (int u = 0; u < 4; u++) {
                const float a = aBuf[(rowg*4+u)*D_ + kc + k];
                acc[u][0] += a*wv.x; acc[u][1] += a*wv.y;
                acc[u][2] += a*wv.z; acc[u][3] += a*wv.w;
            }
        }
    }
    {
        const float4 b2v = ((const float4*)b2_)[colg];
#pragma unroll
        for (int u = 0; u < 4; u++) {
            const size_t row = (size_t)row0 + rowg*4 + u;
            const float4 rv = *(const float4*)(g_R + row*D_ + colg*4);
            float4 o;
            o.x = fmaxf(acc[u][0] + b2v.x, 0.f) + rv.x;
            o.y = fmaxf(acc[u][1] + b2v.y, 0.f) + rv.y;
            o.z = fmaxf(acc[u][2] + b2v.z, 0.f) + rv.z;
            o.w = fmaxf(acc[u][3] + b2v.w, 0.f) + rv.w;
            *(float4*)(outO + row*D_ + colg*4) = o;
        }
    }
}

// ---------------- launch ----------------
extern "C" void kernel_launch(void* const* d_in, const int* in_sizes, int n_in,
                              void* d_out, int out_size) {
    const float* x     = (const float*)d_in[0];
    const float* S0    = (const float*)d_in[1];
    const float* Z0    = (const float*)d_in[2];
    const float* gamma = (const float*)d_in[3];
    const float* beta  = (const float*)d_in[4];
    const float* Wk    = (const float*)d_in[5];
    const float* Wq    = (const float*)d_in[6];
    const float* Wv    = (const float*)d_in[7];
    const float* W1    = (const float*)d_in[8];
    const float* b1    = (const float*)d_in[9];
    const float* W2    = (const float*)d_in[10];
    const float* b2    = (const float*)d_in[11];
    const float* Ws    = (const float*)d_in[12];
    const float* bs    = (const float*)d_in[13];

    float* outO = (float*)d_out;                       // [B,T,D]
    float* outS = outO + (size_t)B_*T_*D_;             // [B,T,D*D]
    float* outZ = outS + (size_t)B_*T_*D_*D_;          // [B,T,D]

    static bool attr_done = false;
    const int smem_k4 = (3*SUB_*D_ + 2*32*D_) * sizeof(float);   // 57344
    if (!attr_done) {
        cudaFuncSetAttribute(k4_main, cudaFuncAttributeMaxDynamicSharedMemorySize, smem_k4);
        attr_done = true;
    }

    const int smem_k1 = (32*FIN_ + 32*D_) * sizeof(float);   // 49152 bytes

    k0_ln<<<(B_*T_)/32, 256>>>(x, gamma, beta);
    k1_proj<<<dim3((B_*T_)/32, 4), 128, smem_k1>>>(Wk, Wq, Wv, Ws, bs);
    k2_chunksum<<<dim3(C_, B_), 256>>>();
    k4_main<<<dim3(C_, B_), 1024, smem_k4>>>(S0, Z0, outS, outZ);
    k5_ffn<<<(B_*T_)/32, 256>>>(W1, b1, W2, b2, outZ, outO);
}

// round 11
// speedup vs baseline: 1.7933x; 1.1808x over previous
#include <cuda_runtime.h>
#include <math.h>
#include <stdint.h>

#define B_   8
#define T_   512
#define FIN_ 256
#define D_   128
#define C_   16          // chunks per batch
#define L_   32          // chunk length (T_/C_)
#define SUB_ 16          // sub-tile of timesteps in k4 smem

// ---------------- scratch ----------------
__device__ __align__(16) float g_XN[B_*T_*FIN_];
__device__ __align__(16) float g_K[B_*T_*D_];
__device__ __align__(16) float g_Q[B_*T_*D_];
__device__ __align__(16) float g_V[B_*T_*D_];
__device__ __align__(16) float g_R[B_*T_*D_];
__device__ __align__(16) float g_num[B_*T_*D_];
__device__ __align__(16) float g_Ssum[B_*C_*D_*D_];  // RAW per-chunk outer sums
__device__ __align__(16) float g_Zsum[B_*C_*D_];     // RAW per-chunk K sums

// ---------------- tf32 helpers ----------------
__device__ __forceinline__ uint32_t f2tf32(float x) {
    uint32_t r; asm("cvt.rna.tf32.f32 %0, %1;" : "=r"(r) : "f"(x)); return r;
}
__device__ __forceinline__ void mma_tf32(float* d, const uint32_t* a, const uint32_t* b) {
    asm volatile(
        "mma.sync.aligned.m16n8k8.row.col.f32.tf32.tf32.f32 "
        "{%0,%1,%2,%3}, {%4,%5,%6,%7}, {%8,%9}, {%0,%1,%2,%3};"
        : "+f"(d[0]), "+f"(d[1]), "+f"(d[2]), "+f"(d[3])
        : "r"(a[0]), "r"(a[1]), "r"(a[2]), "r"(a[3]), "r"(b[0]), "r"(b[1]));
}

// ---------------- k0: LayerNorm -> g_XN ----------------
__global__ void k0_ln(const float* __restrict__ x,
                      const float* __restrict__ gamma, const float* __restrict__ beta) {
    const int tid  = threadIdx.x;
    const int w    = tid >> 5, lane = tid & 31;
    const int row0 = blockIdx.x * 32;

    float gv[8], bv[8];
#pragma unroll
    for (int k = 0; k < 8; k++) { gv[k] = gamma[lane + 32*k]; bv[k] = beta[lane + 32*k]; }

#pragma unroll
    for (int rr = 0; rr < 4; rr++) {
        const size_t r = (size_t)row0 + w*4 + rr;
        float s = 0.f, ss = 0.f, xv[8];
#pragma unroll
        for (int k = 0; k < 8; k++) {
            float v = x[r*FIN_ + lane + 32*k];
            xv[k] = v; s += v; ss += v*v;
        }
#pragma unroll
        for (int off = 16; off; off >>= 1) {
            s  += __shfl_xor_sync(0xffffffffu, s,  off);
            ss += __shfl_xor_sync(0xffffffffu, ss, off);
        }
        const float mu   = s * (1.0f/FIN_);
        const float rstd = rsqrtf(ss*(1.0f/FIN_) - mu*mu + 1e-5f);
#pragma unroll
        for (int k = 0; k < 8; k++)
            g_XN[r*FIN_ + lane + 32*k] = (xv[k]-mu)*rstd*gv[k] + bv[k];
    }
}

// ---------------- k1: tf32 tensor-core projections, 3xTF32 split ----------------
// grid (64, 4) x 256. Block: 64 rows x 128 cols. Warp (wm=wid>>1, wn=wid&1): 16x64.
#define XP 36    // x smem pitch (u32) — conflict-free A frags
#define WP 132   // w smem pitch (u32) — conflict-free B frags
#define K1_SMEM ((2*64*XP + 2*32*WP) * 4)   // 52224 B
__global__ void __launch_bounds__(256)
k1_tf32(const float* __restrict__ Wk, const float* __restrict__ Wq,
        const float* __restrict__ Wv, const float* __restrict__ Ws,
        const float* __restrict__ bs) {
    extern __shared__ uint32_t su[];
    uint32_t* xh = su;                 // [64][XP]
    uint32_t* xl = xh + 64*XP;
    uint32_t* wh = xl + 64*XP;         // [32][WP]
    uint32_t* wl = wh + 32*WP;

    const int tid  = threadIdx.x;
    const int lane = tid & 31;
    const int wid  = tid >> 5;         // 0..7
    const int wm   = wid >> 1;         // 0..3 -> rows wm*16
    const int wn   = wid & 1;          // 0..1 -> cols wn*64
    const int g    = lane >> 2;        // 0..7
    const int t    = lane & 3;         // 0..3
    const int row0 = blockIdx.x * 64;
    const int m    = blockIdx.y;       // 0:K 1:Q 2:V 3:R

    const float* Wp = (m==0) ? Wk : (m==1) ? Wq : (m==2) ? Wv : Ws;
    float*       Op = (m==0) ? g_K : (m==1) ? g_Q : (m==2) ? g_V : g_R;

    float d[8][4];
#pragma unroll
    for (int nt = 0; nt < 8; nt++)
#pragma unroll
        for (int q = 0; q < 4; q++) d[nt][q] = 0.f;

    for (int kc = 0; kc < FIN_; kc += 32) {
        __syncthreads();
        // stage x chunk: 64 rows x 32 k (512 float4)
#pragma unroll
        for (int p = 0; p < 2; p++) {
            const int idx = p*256 + tid;
            const int r = idx >> 3, c4 = (idx & 7) * 4;
            const float4 v = *(const float4*)(g_XN + ((size_t)row0 + r)*FIN_ + kc + c4);
            uint4 h, l;
            h.x = f2tf32(v.x); l.x = f2tf32(v.x - __uint_as_float(h.x));
            h.y = f2tf32(v.y); l.y = f2tf32(v.y - __uint_as_float(h.y));
            h.z = f2tf32(v.z); l.z = f2tf32(v.z - __uint_as_float(h.z));
            h.w = f2tf32(v.w); l.w = f2tf32(v.w - __uint_as_float(h.w));
            *(uint4*)&xh[r*XP + c4] = h;
            *(uint4*)&xl[r*XP + c4] = l;
        }
        // stage w chunk: 32 k x 128 n (1024 float4)
#pragma unroll
        for (int p = 0; p < 4; p++) {
            const int idx = p*256 + tid;
            const int r = idx >> 5, c4 = (idx & 31) * 4;
            const float4 v = *(const float4*)(Wp + ((size_t)kc + r)*D_ + c4);
            uint4 h, l;
            h.x = f2tf32(v.x); l.x = f2tf32(v.x - __uint_as_float(h.x));
            h.y = f2tf32(v.y); l.y = f2tf32(v.y - __uint_as_float(h.y));
            h.z = f2tf32(v.z); l.z = f2tf32(v.z - __uint_as_float(h.z));
            h.w = f2tf32(v.w); l.w = f2tf32(v.w - __uint_as_float(h.w));
            *(uint4*)&wh[r*WP + c4] = h;
            *(uint4*)&wl[r*WP + c4] = l;
        }
        __syncthreads();

#pragma unroll
        for (int ks = 0; ks < 4; ks++) {
            const int ko = ks * 8;
            const int m0 = wm * 16;
            uint32_t ah[4], al[4];
            ah[0] = xh[(m0+g)*XP   + ko + t];
            ah[1] = xh[(m0+g+8)*XP + ko + t];
            ah[2] = xh[(m0+g)*XP   + ko + t + 4];
            ah[3] = xh[(m0+g+8)*XP + ko + t + 4];
            al[0] = xl[(m0+g)*XP   + ko + t];
            al[1] = xl[(m0+g+8)*XP + ko + t];
            al[2] = xl[(m0+g)*XP   + ko + t + 4];
            al[3] = xl[(m0+g+8)*XP + ko + t + 4];
#pragma unroll
            for (int nt = 0; nt < 8; nt++) {
                const int n0 = wn*64 + nt*8;
                uint32_t bh[2], bl[2];
                bh[0] = wh[(ko+t)*WP   + n0 + g];
                bh[1] = wh[(ko+t+4)*WP + n0 + g];
                bl[0] = wl[(ko+t)*WP   + n0 + g];
                bl[1] = wl[(ko+t+4)*WP + n0 + g];
                mma_tf32(d[nt], ah, bh);
                mma_tf32(d[nt], ah, bl);
                mma_tf32(d[nt], al, bh);
            }
        }
    }

    // epilogue: elu+1 (m<=1), +bs (m==3); write float2 pairs
#pragma unroll
    for (int nt = 0; nt < 8; nt++) {
        const int n0 = wn*64 + nt*8;
        const int cA = n0 + t*2;
        float v0 = d[nt][0], v1 = d[nt][1], v2 = d[nt][2], v3 = d[nt][3];
        if (m <= 1) {
            v0 = (v0 > 0.f) ? (v0 + 1.f) : expf(v0);
            v1 = (v1 > 0.f) ? (v1 + 1.f) : expf(v1);
            v2 = (v2 > 0.f) ? (v2 + 1.f) : expf(v2);
            v3 = (v3 > 0.f) ? (v3 + 1.f) : expf(v3);
        } else if (m == 3) {
            const float b0 = bs[cA], b1 = bs[cA+1];
            v0 += b0; v1 += b1; v2 += b0; v3 += b1;
        }
        const size_t r0 = (size_t)row0 + wm*16 + g;
        *(float2*)(Op + r0*D_ + cA)       = make_float2(v0, v1);
        *(float2*)(Op + (r0+8)*D_ + cA)   = make_float2(v2, v3);
    }
}

// ---------------- k2: per-chunk outer-product sums + K sums (RAW) ----------------
__global__ void k2_chunksum() {
    const int c = blockIdx.x, b = blockIdx.y;
    const int tid = threadIdx.x;   // 256
    __shared__ __align__(16) float Ks[L_][D_];
    __shared__ __align__(16) float Vs[L_][D_];
    {
        const float4* kg = (const float4*)(g_K + ((size_t)b*T_ + c*L_)*D_);
        const float4* vg = (const float4*)(g_V + ((size_t)b*T_ + c*L_)*D_);
        for (int q = tid; q < L_*D_/4; q += 256) { ((float4*)Ks)[q] = kg[q]; ((float4*)Vs)[q] = vg[q]; }
    }
    __syncthreads();

    if (tid < D_) {
        float zs = 0.f;
#pragma unroll
        for (int t = 0; t < L_; t++) zs += Ks[t][tid];
        g_Zsum[((size_t)(b*C_ + c))*D_ + tid] = zs;
    }

    const int tr = tid >> 4, tc = tid & 15;
    const int i0 = tr*8, j0 = tc*8;
    float acc[8][8];
#pragma unroll
    for (int u = 0; u < 8; u++)
#pragma unroll
        for (int v = 0; v < 8; v++) acc[u][v] = 0.f;

    for (int t = 0; t < L_; t++) {
        float k8[8], v8[8];
        *(float4*)(k8)   = *(const float4*)&Ks[t][i0];
        *(float4*)(k8+4) = *(const float4*)&Ks[t][i0+4];
        *(float4*)(v8)   = *(const float4*)&Vs[t][j0];
        *(float4*)(v8+4) = *(const float4*)&Vs[t][j0+4];
#pragma unroll
        for (int u = 0; u < 8; u++)
#pragma unroll
            for (int v = 0; v < 8; v++) acc[u][v] += k8[u]*v8[v];
    }
    float* op = g_Ssum + (((size_t)(b*C_ + c))*D_ + i0)*D_ + j0;
#pragma unroll
    for (int u = 0; u < 8; u++) {
        *(float4*)(op + (size_t)u*D_)     = make_float4(acc[u][0],acc[u][1],acc[u][2],acc[u][3]);
        *(float4*)(op + (size_t)u*D_ + 4) = make_float4(acc[u][4],acc[u][5],acc[u][6],acc[u][7]);
    }
}

// ---------------- k4: fused scan — S state in regs, write S + Z, num inline ----------------
__global__ void __launch_bounds__(1024, 1)
k4_main(const float* __restrict__ S0, const float* __restrict__ Z0,
        float* __restrict__ outS, float* __restrict__ outZ) {
    const int c = blockIdx.x, b = blockIdx.y;
    const int tid = threadIdx.x;         // 1024
    const int ri = tid >> 5;             // 0..31
    const int jg = tid & 31;             // 0..31
    const int i0 = ri << 2, j0 = jg << 2;

    extern __shared__ float dsm[];
    float* Ks   = dsm;                         // [SUB_][D_]
    float* Vs   = Ks + SUB_*D_;
    float* Qs   = Vs + SUB_*D_;
    float* part = Qs + SUB_*D_;                // [2][32][D_]

    // init: S0 + sum of raw chunk sums c' < c
    float s[4][4];
    {
        const float* s0g = S0 + ((size_t)b*D_ + i0)*D_ + j0;
#pragma unroll
        for (int u = 0; u < 4; u++) {
            const float4 z = *(const float4*)(s0g + (size_t)u*D_);
            s[u][0] = z.x; s[u][1] = z.y; s[u][2] = z.z; s[u][3] = z.w;
        }
        for (int c2 = 0; c2 < c; c2++) {
            const float* sp = g_Ssum + ((size_t)(b*C_ + c2)*D_ + i0)*D_ + j0;
#pragma unroll
            for (int u = 0; u < 4; u++) {
                const float4 a = __ldg((const float4*)(sp + (size_t)u*D_));
                s[u][0] += a.x; s[u][1] += a.y; s[u][2] += a.z; s[u][3] += a.w;
            }
        }
    }

    float zrun = 0.f;
    if (tid < D_) {
        zrun = Z0[b*D_ + tid];
        for (int c2 = 0; c2 < c; c2++)
            zrun += g_Zsum[(size_t)(b*C_ + c2)*D_ + tid];
    }

    const int t0 = c * L_;
    for (int sub = 0; sub < L_/SUB_; sub++) {
        const int tg = t0 + sub*SUB_;
        {
            const float4* kg = (const float4*)(g_K + ((size_t)b*T_ + tg)*D_);
            const float4* vg = (const float4*)(g_V + ((size_t)b*T_ + tg)*D_);
            const float4* qg = (const float4*)(g_Q + ((size_t)b*T_ + tg)*D_);
            const int h = tid & 511;
            if (tid < 512) { ((float4*)Ks)[h] = kg[h]; ((float4*)Vs)[h] = vg[h]; }
            else           { ((float4*)Qs)[h] = qg[h]; }
        }
        __syncthreads();

        for (int tt = 0; tt < SUB_; tt++) {
            const int t = tg + tt;
            const float4 kv = *(const float4*)&Ks[tt*D_ + i0];
            const float4 vv = *(const float4*)&Vs[tt*D_ + j0];
            const float4 qv = *(const float4*)&Qs[tt*D_ + i0];
            const float kk[4] = {kv.x, kv.y, kv.z, kv.w};
            const float vb[4] = {vv.x, vv.y, vv.z, vv.w};
            const float qq[4] = {qv.x, qv.y, qv.z, qv.w};
            float p0 = 0.f, p1 = 0.f, p2 = 0.f, p3 = 0.f;
            float* orow = outS + (((size_t)b*T_ + t)*D_ + i0)*D_ + j0;
#pragma unroll
            for (int u = 0; u < 4; u++) {
                s[u][0] += kk[u]*vb[0];
                s[u][1] += kk[u]*vb[1];
                s[u][2] += kk[u]*vb[2];
                s[u][3] += kk[u]*vb[3];
                __stcs((float4*)(orow + (size_t)u*D_),
                       make_float4(s[u][0], s[u][1], s[u][2], s[u][3]));
                p0 += qq[u]*s[u][0];
                p1 += qq[u]*s[u][1];
                p2 += qq[u]*s[u][2];
                p3 += qq[u]*s[u][3];
            }
            float* pb = part + (tt & 1)*32*D_;
            *(float4*)&pb[ri*D_ + j0] = make_float4(p0, p1, p2, p3);
            if (tid < D_) {
                zrun += Ks[tt*D_ + tid];
                outZ[((size_t)b*T_ + t)*D_ + tid] = zrun;
            }
            __syncthreads();
            if (tid < D_) {
                float sum = 0.f;
#pragma unroll
                for (int rr = 0; rr < 32; rr++) sum += pb[rr*D_ + tid];
                g_num[((size_t)b*T_ + t)*D_ + tid] = sum;
            }
        }
        __syncthreads();
    }
}

// ---------------- k5: out = relu(relu((num/den)@W1+b1)@W2+b2) + R ----------------
__global__ void k5_ffn(const float* __restrict__ W1, const float* __restrict__ b1_,
                       const float* __restrict__ W2, const float* __restrict__ b2_,
                       const float* __restrict__ Zout, float* __restrict__ outO) {
    __shared__ __align__(16) float aBuf[32*D_];
    __shared__ __align__(16) float wBuf[32*D_];
    const int tid  = threadIdx.x;  // 256
    const int w    = tid >> 5, lane = tid & 31;
    const int row0 = blockIdx.x * 32;

#pragma unroll
    for (int rr = 0; rr < 4; rr++) {
        const int r = w*4 + rr;
        const size_t row = (size_t)row0 + r;
        float d = 0.f;
#pragma unroll
        for (int k = 0; k < 4; k++) {
            const int f = lane + 32*k;
            d += g_Q[row*D_ + f] * Zout[row*D_ + f];
        }
#pragma unroll
        for (int off = 16; off; off >>= 1) d += __shfl_xor_sync(0xffffffffu, d, off);
        const float rden = 1.0f / (d + 1e-5f);
#pragma unroll
        for (int k = 0; k < 4; k++) {
            const int f = lane + 32*k;
            aBuf[r*D_ + f] = g_num[row*D_ + f] * rden;
        }
    }
    const int rowg = w, colg = lane;
    float acc[4][4];

#pragma unroll
    for (int u = 0; u < 4; u++)
#pragma unroll
        for (int v = 0; v < 4; v++) acc[u][v] = 0.f;
    for (int kc = 0; kc < D_; kc += 32) {
        __syncthreads();
        for (int q = tid; q < 32*D_/4; q += 256)
            ((float4*)wBuf)[q] = ((const float4*)(W1 + (size_t)kc*D_))[q];
        __syncthreads();
#pragma unroll
        for (int k = 0; k < 32; k++) {
            const float4 wv = ((const float4*)(wBuf + k*D_))[colg];
#pragma unroll
            for (int u = 0; u < 4; u++) {
                const float a = aBuf[(rowg*4+u)*D_ + kc + k];
                acc[u][0] += a*wv.x; acc[u][1] += a*wv.y;
                acc[u][2] += a*wv.z; acc[u][3] += a*wv.w;
            }
        }
    }
    __syncthreads();
    {
        const float4 b1v = ((const float4*)b1_)[colg];
#pragma unroll
        for (int u = 0; u < 4; u++) {
            float4 h;
            h.x = fmaxf(acc[u][0] + b1v.x, 0.f);
            h.y = fmaxf(acc[u][1] + b1v.y, 0.f);
            h.z = fmaxf(acc[u][2] + b1v.z, 0.f);
            h.w = fmaxf(acc[u][3] + b1v.w, 0.f);
            *(float4*)&aBuf[(rowg*4+u)*D_ + colg*4] = h;
        }
    }
#pragma unroll
    for (int u = 0; u < 4; u++)
#pragma unroll
        for (int v = 0; v < 4; v++) acc[u][v] = 0.f;
    for (int kc = 0; kc < D_; kc += 32) {
        __syncthreads();
        for (int q = tid; q < 32*D_/4; q += 256)
            ((float4*)wBuf)[q] = ((const float4*)(W2 + (size_t)kc*D_))[q];
        __syncthreads();
#pragma unroll
        for (int k = 0; k < 32; k++) {
            const float4 wv = ((const float4*)(wBuf + k*D_))[colg];
#pragma unroll
            for (int u = 0; u < 4; u++) {
                const float a = aBuf[(rowg*4+u)*D_ + kc + k];
                acc[u][0] += a*wv.x; acc[u][1] += a*wv.y;
                acc[u][2] += a*wv.z; acc[u][3] += a*wv.w;
            }
        }
    }
    {
        const float4 b2v = ((const float4*)b2_)[colg];
#pragma unroll
        for (int u = 0; u < 4; u++) {
            const size_t row = (size_t)row0 + rowg*4 + u;
            const float4 rv = *(const float4*)(g_R + row*D_ + colg*4);
            float4 o;
            o.x = fmaxf(acc[u][0] + b2v.x, 0.f) + rv.x;
            o.y = fmaxf(acc[u][1] + b2v.y, 0.f) + rv.y;
            o.z = fmaxf(acc[u][2] + b2v.z, 0.f) + rv.z;
            o.w = fmaxf(acc[u][3] + b2v.w, 0.f) + rv.w;
            *(float4*)(outO + row*D_ + colg*4) = o;
        }
    }
}

// ---------------- launch ----------------
extern "C" void kernel_launch(void* const* d_in, const int* in_sizes, int n_in,
                              void* d_out, int out_size) {
    const float* x     = (const float*)d_in[0];
    const float* S0    = (const float*)d_in[1];
    const float* Z0    = (const float*)d_in[2];
    const float* gamma = (const float*)d_in[3];
    const float* beta  = (const float*)d_in[4];
    const float* Wk    = (const float*)d_in[5];
    const float* Wq    = (const float*)d_in[6];
    const float* Wv    = (const float*)d_in[7];
    const float* W1    = (const float*)d_in[8];
    const float* b1    = (const float*)d_in[9];
    const float* W2    = (const float*)d_in[10];
    const float* b2    = (const float*)d_in[11];
    const float* Ws    = (const float*)d_in[12];
    const float* bs    = (const float*)d_in[13];

    float* outO = (float*)d_out;
    float* outS = outO + (size_t)B_*T_*D_;
    float* outZ = outS + (size_t)B_*T_*D_*D_;

    static bool attr_done = false;
    const int smem_k4 = (3*SUB_*D_ + 2*32*D_) * sizeof(float);   // 57344
    if (!attr_done) {
        cudaFuncSetAttribute(k4_main, cudaFuncAttributeMaxDynamicSharedMemorySize, smem_k4);
        cudaFuncSetAttribute(k1_tf32, cudaFuncAttributeMaxDynamicSharedMemorySize, K1_SMEM);
        attr_done = true;
    }

    k0_ln<<<(B_*T_)/32, 256>>>(x, gamma, beta);
    k1_tf32<<<dim3((B_*T_)/64, 4), 256, K1_SMEM>>>(Wk, Wq, Wv, Ws, bs);
    k2_chunksum<<<dim3(C_, B_), 256>>>();
    k4_main<<<dim3(C_, B_), 1024, smem_k4>>>(S0, Z0, outS, outZ);
    k5_ffn<<<(B_*T_)/32, 256>>>(W1, b1, W2, b2, outZ, outO);
}